// round 8
// baseline (speedup 1.0000x reference)
#include <cuda_runtime.h>
#include <cuda_bf16.h>
#include <math.h>

// ---------------- constants ----------------
#define TPIF 6.283185307179586f
// output section offsets (floats)
#define OFF_Y    0
#define OFF_LAT  276480
#define OFF_SIG  291968
#define OFF_P    307456
#define OFF_FQ   307584
#define OFF_A    307712
#define OFF_B    307840
#define OFF_YP   307968

// ---------------- scratch ----------------
__device__ float  g_P[(size_t)16*24*121*240];   // S then k-prefix: [b][o][k][Q]
__device__ float  g_w2t[24*121*8];              // enc_w2 transposed [o][k][e]
__device__ float2 g_twid[121*64];               // twiddles [t][f]
__device__ float  g_ys[(size_t)16*8*240*121];   // ysin [b][e][n][t]
__device__ float  g_scy[16*8*360];              // padded yc
__device__ float  g_dpre[16*24*240];            // dec conv1 pre-BN
__device__ float  g_bnm[24];
__device__ float  g_bni[24];
__device__ float  g_ddp[16*24*360];             // tanh(BN(d)) padded

#define FULLMASK 0xffffffffu
__device__ __forceinline__ float wred(float v) {
    v += __shfl_xor_sync(FULLMASK, v, 16);
    v += __shfl_xor_sync(FULLMASK, v, 8);
    v += __shfl_xor_sync(FULLMASK, v, 4);
    v += __shfl_xor_sync(FULLMASK, v, 2);
    v += __shfl_xor_sync(FULLMASK, v, 1);
    return v;
}

// ---------------- prep: twiddles + w2 transpose ----------------
__global__ void prep_k(const float* __restrict__ w2) {
    int i = blockIdx.x * blockDim.x + threadIdx.x;
    int stride = gridDim.x * blockDim.x;
    for (int idx = i; idx < 121 * 61; idx += stride) {
        int t = idx / 61, f = idx - 61 * t;
        float fr = (float)fmod((double)(2 * f * t) / 121.0, 2.0);
        float sn, cs; sincospif(fr, &sn, &cs);
        g_twid[t * 64 + f] = make_float2(cs, sn);
    }
    for (int idx = i; idx < 24 * 121 * 8; idx += stride) {
        int e = idx & 7, ok = idx >> 3;
        int o = ok / 121, k = ok - 121 * o;
        g_w2t[idx] = w2[(e * 24 + o) * 121 + k];
    }
}

// ---------------- S[b,o,k,Q] ----------------
__global__ void __launch_bounds__(256) s_kernel(const float* __restrict__ x,
                                                const float* __restrict__ w1) {
    extern __shared__ float sm[];
    float* xs = sm;               // 72 x 244 (dup-padded)
    float* ws = sm + 72 * 244;    // 24 x 72
    const int k = blockIdx.x, b = blockIdx.y;
    const int tid = threadIdx.x;

    for (int idx = tid; idx < 72 * 240; idx += 256) {
        int i = idx / 240, c = idx - 240 * i;
        xs[i * 244 + c] = x[(b * 72 + i) * 240 + c];
    }
    for (int idx = tid; idx < 72 * 4; idx += 256) {
        int i = idx >> 2, j = idx & 3;
        xs[i * 244 + 240 + j] = x[(b * 72 + i) * 240 + j];
    }
    for (int idx = tid; idx < 24 * 72; idx += 256)
        ws[idx] = w1[idx * 121 + k];
    __syncthreads();

    for (int task = tid; task < 360; task += 256) {
        int og = task / 60, qg = task - 60 * og;
        int o0 = og * 4, Q0 = qg * 4;
        float acc[4][4];
        #pragma unroll
        for (int a = 0; a < 4; a++)
            #pragma unroll
            for (int q = 0; q < 4; q++) acc[a][q] = 0.f;
        int base = Q0 + k + 120; if (base >= 240) base -= 240;
        const float* xb = xs + base;
        const float* wp0 = ws + (o0 + 0) * 72;
        const float* wp1 = ws + (o0 + 1) * 72;
        const float* wp2 = ws + (o0 + 2) * 72;
        const float* wp3 = ws + (o0 + 3) * 72;
        #pragma unroll 4
        for (int i = 0; i < 72; i++) {
            const float* xr = xb + i * 244;
            float x0 = xr[0], x1 = xr[1], x2 = xr[2], x3 = xr[3];
            float w0 = wp0[i], w1v = wp1[i], w2v = wp2[i], w3v = wp3[i];
            acc[0][0]=fmaf(w0,x0,acc[0][0]); acc[0][1]=fmaf(w0,x1,acc[0][1]);
            acc[0][2]=fmaf(w0,x2,acc[0][2]); acc[0][3]=fmaf(w0,x3,acc[0][3]);
            acc[1][0]=fmaf(w1v,x0,acc[1][0]); acc[1][1]=fmaf(w1v,x1,acc[1][1]);
            acc[1][2]=fmaf(w1v,x2,acc[1][2]); acc[1][3]=fmaf(w1v,x3,acc[1][3]);
            acc[2][0]=fmaf(w2v,x0,acc[2][0]); acc[2][1]=fmaf(w2v,x1,acc[2][1]);
            acc[2][2]=fmaf(w2v,x2,acc[2][2]); acc[2][3]=fmaf(w2v,x3,acc[2][3]);
            acc[3][0]=fmaf(w3v,x0,acc[3][0]); acc[3][1]=fmaf(w3v,x1,acc[3][1]);
            acc[3][2]=fmaf(w3v,x2,acc[3][2]); acc[3][3]=fmaf(w3v,x3,acc[3][3]);
        }
        size_t pbase = ((size_t)(b * 24 + o0) * 121 + k) * 240 + Q0;
        #pragma unroll
        for (int oo = 0; oo < 4; oo++)
            #pragma unroll
            for (int qq = 0; qq < 4; qq++)
                g_P[pbase + (size_t)oo * 121 * 240 + qq] = acc[oo][qq];
    }
}

// ---------------- prefix over k ----------------
__global__ void prefix_k() {
    int bo = blockIdx.x, Q = threadIdx.x;
    if (Q < 240) {
        size_t base = (size_t)bo * 121 * 240 + Q;
        float acc = 0.f;
        for (int k = 0; k < 121; k++) {
            acc += g_P[base + (size_t)k * 240];
            g_P[base + (size_t)k * 240] = acc;
        }
    }
}

// ---------------- encoder: conv1(LN,tanh) + conv2 + DFT + params + ysin ----------------
// one warp per window; block = 4 warps
__global__ void __launch_bounds__(128, 2) encode_k(
    const float* __restrict__ lna, const float* __restrict__ lnb,
    const float* __restrict__ b2, const float* __restrict__ fcw,
    const float* __restrict__ fcb, float* __restrict__ out)
{
    extern __shared__ float sm[];
    const int warp = threadIdx.x >> 5, lane = threadIdx.x & 31;
    float* hp = sm + warp * 6000;            // 24 x 250 zero-padded h
    float* lt = sm + 24000 + warp * 976;     // 8 x 122 latent
    const int s = blockIdx.x * 4 + warp;
    const int b = s / 240, n = s - b * 240;

    for (int i = lane; i < 6000; i += 32) hp[i] = 0.f;
    __syncwarp();

    // conv1 via prefix differences + LayerNorm + tanh
    const size_t pb0 = (size_t)(b * 24) * 121 * 240;
    for (int o = 0; o < 24; o++) {
        const float* P = g_P + pb0 + (size_t)o * 121 * 240;
        float hv[4]; float s1 = 0.f, s2 = 0.f;
        #pragma unroll
        for (int j = 0; j < 4; j++) {
            int t = lane + 32 * j;
            float h = 0.f;
            if (t < 121) {
                int Q = n + t; if (Q >= 240) Q -= 240;
                if (t < 60) h = P[120 * 240 + Q] - P[(59 - t) * 240 + Q];
                else        h = P[(180 - t) * 240 + Q];
                s1 += h; s2 += h * h;
            }
            hv[j] = h;
        }
        s1 = wred(s1); s2 = wred(s2);
        float mean = s1 * (1.f / 121.f);
        float var = (s2 - s1 * mean) * (1.f / 120.f);
        float inv = 1.f / (sqrtf(var) + 1e-5f);
        #pragma unroll
        for (int j = 0; j < 4; j++) {
            int t = lane + 32 * j;
            if (t < 121)
                hp[o * 250 + 60 + t] = tanhf((hv[j] - mean) * inv * lna[t] + lnb[t]);
        }
    }
    __syncwarp();

    // conv2: 8e x 4t register tile per lane
    float acc[8][4];
    #pragma unroll
    for (int e = 0; e < 8; e++)
        #pragma unroll
        for (int j = 0; j < 4; j++) acc[e][j] = 0.f;

    for (int o = 0; o < 24; o++) {
        const float* hpo = hp + o * 250 + lane;
        const float4* wrow = (const float4*)(g_w2t + o * 121 * 8);
        #pragma unroll 4
        for (int k = 0; k < 121; k++) {
            float4 wa = wrow[2 * k], wb = wrow[2 * k + 1];
            float x0 = hpo[k], x1 = hpo[k + 32], x2 = hpo[k + 64], x3 = hpo[k + 96];
            acc[0][0]=fmaf(wa.x,x0,acc[0][0]); acc[0][1]=fmaf(wa.x,x1,acc[0][1]);
            acc[0][2]=fmaf(wa.x,x2,acc[0][2]); acc[0][3]=fmaf(wa.x,x3,acc[0][3]);
            acc[1][0]=fmaf(wa.y,x0,acc[1][0]); acc[1][1]=fmaf(wa.y,x1,acc[1][1]);
            acc[1][2]=fmaf(wa.y,x2,acc[1][2]); acc[1][3]=fmaf(wa.y,x3,acc[1][3]);
            acc[2][0]=fmaf(wa.z,x0,acc[2][0]); acc[2][1]=fmaf(wa.z,x1,acc[2][1]);
            acc[2][2]=fmaf(wa.z,x2,acc[2][2]); acc[2][3]=fmaf(wa.z,x3,acc[2][3]);
            acc[3][0]=fmaf(wa.w,x0,acc[3][0]); acc[3][1]=fmaf(wa.w,x1,acc[3][1]);
            acc[3][2]=fmaf(wa.w,x2,acc[3][2]); acc[3][3]=fmaf(wa.w,x3,acc[3][3]);
            acc[4][0]=fmaf(wb.x,x0,acc[4][0]); acc[4][1]=fmaf(wb.x,x1,acc[4][1]);
            acc[4][2]=fmaf(wb.x,x2,acc[4][2]); acc[4][3]=fmaf(wb.x,x3,acc[4][3]);
            acc[5][0]=fmaf(wb.y,x0,acc[5][0]); acc[5][1]=fmaf(wb.y,x1,acc[5][1]);
            acc[5][2]=fmaf(wb.y,x2,acc[5][2]); acc[5][3]=fmaf(wb.y,x3,acc[5][3]);
            acc[6][0]=fmaf(wb.z,x0,acc[6][0]); acc[6][1]=fmaf(wb.z,x1,acc[6][1]);
            acc[6][2]=fmaf(wb.z,x2,acc[6][2]); acc[6][3]=fmaf(wb.z,x3,acc[6][3]);
            acc[7][0]=fmaf(wb.w,x0,acc[7][0]); acc[7][1]=fmaf(wb.w,x1,acc[7][1]);
            acc[7][2]=fmaf(wb.w,x2,acc[7][2]); acc[7][3]=fmaf(wb.w,x3,acc[7][3]);
        }
    }
    #pragma unroll
    for (int e = 0; e < 8; e++) {
        float be = b2[e];
        #pragma unroll
        for (int j = 0; j < 4; j++) {
            int t = lane + 32 * j;
            if (t < 121) lt[e * 122 + t] = acc[e][j] + be;
        }
    }
    __syncwarp();

    // DC term and fc phase projections
    float bo_[8], v0[8], v1[8];
    #pragma unroll
    for (int e = 0; e < 8; e++) {
        float sb = 0.f, sv0 = 0.f, sv1 = 0.f;
        for (int t = lane; t < 121; t += 32) {
            float l = lt[e * 122 + t];
            sb += l;
            sv0 = fmaf(l, fcw[(e * 2 + 0) * 121 + t], sv0);
            sv1 = fmaf(l, fcw[(e * 2 + 1) * 121 + t], sv1);
        }
        bo_[e] = wred(sb) * (1.f / 121.f);
        v0[e] = wred(sv0) + fcb[e * 2];
        v1[e] = wred(sv1) + fcb[e * 2 + 1];
    }

    // direct DFT, bins 1..60 spread over lanes
    float num[8], den[8];
    #pragma unroll
    for (int e = 0; e < 8; e++) { num[e] = 0.f; den[e] = 0.f; }
    #pragma unroll
    for (int half = 0; half < 2; half++) {
        int fi = lane + 32 * half;
        if (fi < 60) {
            float cr[8], ci[8];
            #pragma unroll
            for (int e = 0; e < 8; e++) { cr[e] = 0.f; ci[e] = 0.f; }
            for (int t = 0; t < 121; t++) {
                float2 w = g_twid[t * 64 + fi + 1];
                #pragma unroll
                for (int e = 0; e < 8; e++) {
                    float l = lt[e * 122 + t];
                    cr[e] = fmaf(l, w.x, cr[e]);
                    ci[e] = fmaf(l, w.y, ci[e]);
                }
            }
            float fr = 0.5f * (float)(fi + 1);
            #pragma unroll
            for (int e = 0; e < 8; e++) {
                float pw = cr[e] * cr[e] + ci[e] * ci[e];
                num[e] = fmaf(pw, fr, num[e]);
                den[e] += pw;
            }
        }
    }
    #pragma unroll
    for (int e = 0; e < 8; e++) { num[e] = wred(num[e]); den[e] = wred(den[e]); }

    float fe[8], am[8], ph[8];
    #pragma unroll
    for (int e = 0; e < 8; e++) {
        fe[e] = num[e] / den[e];
        am[e] = 2.f * sqrtf(den[e]) * (1.f / 121.f);
        ph[e] = atan2f(v1[e], v0[e]);
    }

    if (n == 0) {
        if (lane == 0) {
            #pragma unroll
            for (int e = 0; e < 8; e++) {
                out[OFF_P  + b * 8 + e] = ph[e] * (1.f / TPIF);
                out[OFF_FQ + b * 8 + e] = fe[e];
                out[OFF_A  + b * 8 + e] = am[e];
                out[OFF_B  + b * 8 + e] = bo_[e];
            }
        }
        #pragma unroll
        for (int e = 0; e < 8; e++)
            for (int t = lane; t < 121; t += 32)
                out[OFF_LAT + (b * 8 + e) * 121 + t] = lt[e * 122 + t];
    }

    // sinusoid resynthesis
    #pragma unroll
    for (int e = 0; e < 8; e++) {
        float* yd = g_ys + ((size_t)(b * 8 + e) * 240 + n) * 121;
        float w = TPIF * fe[e];
        for (int t = lane; t < 121; t += 32) {
            float arg = fmaf(w, (float)(t - 60) * (1.f / 60.f), ph[e]);
            yd[t] = fmaf(am[e], sinf(arg), bo_[e]);
        }
    }
}

// ---------------- overlap-add (deterministic gather) ----------------
__global__ void overlap_k(float* __restrict__ out) {
    int be = blockIdx.x;
    int j = threadIdx.x; // 0..359
    const float* ys = g_ys + (size_t)be * 240 * 121;
    int tlo = j - 239; if (tlo < 0) tlo = 0;
    int thi = j < 120 ? j : 120;
    float s = 0.f;
    for (int t = tlo; t <= thi; t++) s += ys[(j - t) * 121 + t];
    float w = (j < 121) ? (float)(j + 1) : (j > 239 ? (float)(360 - j) : 121.f);
    float sig = s / w;
    if (j < 121) out[OFF_SIG + be * 121 + j] = sig;
    g_scy[be * 360 + j] = (j >= 60 && j < 300) ? sig : 0.f;
}

// ---------------- decoder conv1 (bias skipped: cancels in BN) ----------------
__global__ void __launch_bounds__(256) dec1_k(const float* __restrict__ dw1) {
    __shared__ float ys[8 * 360], ws[8 * 121];
    int b = blockIdx.x, o = blockIdx.y, tid = threadIdx.x;
    for (int i = tid; i < 8 * 360; i += 256)
        ys[i] = g_scy[(b * 8 + i / 360) * 360 + i % 360];
    for (int i = tid; i < 8 * 121; i += 256)
        ws[i] = dw1[o * 8 * 121 + i];
    __syncthreads();
    if (tid < 240) {
        float acc = 0.f;
        #pragma unroll
        for (int e = 0; e < 8; e++) {
            const float* yr = ys + e * 360 + tid;
            const float* wr = ws + e * 121;
            #pragma unroll 4
            for (int k = 0; k < 121; k++) acc = fmaf(wr[k], yr[k], acc);
        }
        g_dpre[(b * 24 + o) * 240 + tid] = acc;
    }
}

// ---------------- BN stats (deterministic tree) ----------------
__global__ void bnstat_k() {
    __shared__ float r1[256], r2[256];
    int o = blockIdx.x, tid = threadIdx.x;
    float s1 = 0.f, s2 = 0.f;
    for (int i = tid; i < 3840; i += 256) {
        int bb = i / 240, t = i - 240 * bb;
        float v = g_dpre[(bb * 24 + o) * 240 + t];
        s1 += v; s2 += v * v;
    }
    r1[tid] = s1; r2[tid] = s2; __syncthreads();
    for (int st = 128; st > 0; st >>= 1) {
        if (tid < st) { r1[tid] += r1[tid + st]; r2[tid] += r2[tid + st]; }
        __syncthreads();
    }
    if (tid == 0) {
        float m = r1[0] * (1.f / 3840.f);
        g_bnm[o] = m;
        g_bni[o] = rsqrtf(r2[0] * (1.f / 3840.f) - m * m + 1e-5f);
    }
}

__global__ void bnapply_k(const float* __restrict__ gam, const float* __restrict__ bet) {
    int idx = blockIdx.x * blockDim.x + threadIdx.x;
    if (idx >= 16 * 24 * 360) return;
    int tau = idx % 360, bo = idx / 360;
    int o = bo % 24;
    float v = 0.f;
    if (tau >= 60 && tau < 300)
        v = tanhf((g_dpre[bo * 240 + tau - 60] - g_bnm[o]) * g_bni[o] * gam[o] + bet[o]);
    g_ddp[idx] = v;
}

// ---------------- decoder conv2 + outputs ----------------
__global__ void __launch_bounds__(64) dec2_k(const float* __restrict__ dw2,
                                             const float* __restrict__ db2,
                                             float* __restrict__ out) {
    __shared__ float dd[24 * 360], ws[24 * 121];
    int b = blockIdx.x, c = blockIdx.y, tid = threadIdx.x;
    for (int i = tid; i < 24 * 360; i += 64) dd[i] = g_ddp[b * 24 * 360 + i];
    for (int i = tid; i < 24 * 121; i += 64) ws[i] = dw2[c * 24 * 121 + i];
    __syncthreads();
    if (tid < 60) {
        int t0 = tid * 4;
        float a0 = 0.f, a1 = 0.f, a2 = 0.f, a3 = 0.f;
        for (int o = 0; o < 24; o++) {
            const float* dr = dd + o * 360 + t0;
            const float* wr = ws + o * 121;
            float x0 = dr[0], x1 = dr[1], x2 = dr[2];
            #pragma unroll 4
            for (int k = 0; k < 121; k++) {
                float w = wr[k]; float x3 = dr[k + 3];
                a0 = fmaf(w, x0, a0); a1 = fmaf(w, x1, a1);
                a2 = fmaf(w, x2, a2); a3 = fmaf(w, x3, a3);
                x0 = x1; x1 = x2; x2 = x3;
            }
        }
        float bias = db2[c];
        float r[4] = { a0 + bias, a1 + bias, a2 + bias, a3 + bias };
        size_t yb = (size_t)(b * 72 + c) * 240 + t0;
        #pragma unroll
        for (int q = 0; q < 4; q++) {
            out[OFF_Y + yb + q] = r[q];
            int t = t0 + q;
            if (t < 121) out[OFF_YP + (b * 72 + c) * 121 + t] = r[q];
        }
    }
}

// ---------------- launch ----------------
extern "C" void kernel_launch(void* const* d_in, const int* in_sizes, int n_in,
                              void* d_out, int out_size) {
    const float* x   = (const float*)d_in[0];
    const float* w1  = (const float*)d_in[1];
    const float* lna = (const float*)d_in[3];
    const float* lnb = (const float*)d_in[4];
    const float* w2  = (const float*)d_in[5];
    const float* b2  = (const float*)d_in[6];
    const float* fcw = (const float*)d_in[7];
    const float* fcb = (const float*)d_in[8];
    const float* dw1 = (const float*)d_in[9];
    const float* bng = (const float*)d_in[11];
    const float* bnb = (const float*)d_in[12];
    const float* dw2 = (const float*)d_in[13];
    const float* db2 = (const float*)d_in[14];
    float* out = (float*)d_out;

    const int SMEM_S = (72 * 244 + 24 * 72) * 4;      // 77184
    const int SMEM_E = (4 * (6000 + 976)) * 4;        // 111616
    cudaFuncSetAttribute(s_kernel, cudaFuncAttributeMaxDynamicSharedMemorySize, SMEM_S);
    cudaFuncSetAttribute(encode_k, cudaFuncAttributeMaxDynamicSharedMemorySize, SMEM_E);

    prep_k<<<64, 256>>>(w2);
    s_kernel<<<dim3(121, 16), 256, SMEM_S>>>(x, w1);
    prefix_k<<<384, 256>>>();
    encode_k<<<960, 128, SMEM_E>>>(lna, lnb, b2, fcw, fcb, out);
    overlap_k<<<128, 360>>>(out);
    dec1_k<<<dim3(16, 24), 256>>>(dw1);
    bnstat_k<<<24, 256>>>();
    bnapply_k<<<540, 256>>>(bng, bnb);
    dec2_k<<<dim3(16, 72), 64>>>(dw2, db2, out);
}

// round 10
// speedup vs baseline: 1.5927x; 1.5927x over previous
#include <cuda_runtime.h>
#include <cuda_bf16.h>
#include <math.h>

// ---------------- constants ----------------
#define TPIF 6.283185307179586f
// output section offsets (floats)
#define OFF_Y    0
#define OFF_LAT  276480
#define OFF_SIG  291968
#define OFF_P    307456
#define OFF_FQ   307584
#define OFF_A    307712
#define OFF_B    307840
#define OFF_YP   307968

// ---------------- scratch ----------------
__device__ float  g_P[(size_t)16*24*121*240];   // S then k-prefix: [b][o][k][Q]
__device__ float  g_w2t[24*121*8];              // enc_w2 transposed [o][k][e]
__device__ float2 g_twid[121*64];               // twiddles [t][f]
__device__ float  g_ys[(size_t)16*8*240*121];   // ysin [b][e][n][t]
__device__ float  g_scy[16*8*360];              // padded yc
__device__ float  g_dpre[16*24*240];            // dec conv1 pre-BN
__device__ float  g_bnm[24];
__device__ float  g_bni[24];
__device__ float  g_ddp[16*24*360];             // tanh(BN(d)) padded

#define FULLMASK 0xffffffffu
__device__ __forceinline__ float wred(float v) {
    v += __shfl_xor_sync(FULLMASK, v, 16);
    v += __shfl_xor_sync(FULLMASK, v, 8);
    v += __shfl_xor_sync(FULLMASK, v, 4);
    v += __shfl_xor_sync(FULLMASK, v, 2);
    v += __shfl_xor_sync(FULLMASK, v, 1);
    return v;
}

// packed f32x2 helpers
__device__ __forceinline__ unsigned long long dup2(float x) {
    unsigned long long r; unsigned u = __float_as_uint(x);
    asm("mov.b64 %0, {%1, %1};" : "=l"(r) : "r"(u));
    return r;
}
__device__ __forceinline__ void ffma2(unsigned long long& d, unsigned long long a, unsigned long long b) {
    asm("fma.rn.f32x2 %0, %1, %2, %0;" : "+l"(d) : "l"(a), "l"(b));
}
__device__ __forceinline__ float2 unpack2(unsigned long long v) {
    unsigned lo, hi;
    asm("mov.b64 {%0, %1}, %2;" : "=r"(lo), "=r"(hi) : "l"(v));
    return make_float2(__uint_as_float(lo), __uint_as_float(hi));
}

// ---------------- prep: twiddles + w2 transpose ----------------
__global__ void prep_k(const float* __restrict__ w2) {
    int i = blockIdx.x * blockDim.x + threadIdx.x;
    int stride = gridDim.x * blockDim.x;
    for (int idx = i; idx < 121 * 61; idx += stride) {
        int t = idx / 61, f = idx - 61 * t;
        float fr = (float)fmod((double)(2 * f * t) / 121.0, 2.0);
        float sn, cs; sincospif(fr, &sn, &cs);
        g_twid[t * 64 + f] = make_float2(cs, sn);
    }
    for (int idx = i; idx < 24 * 121 * 8; idx += stride) {
        int e = idx & 7, ok = idx >> 3;
        int o = ok / 121, k = ok - 121 * o;
        g_w2t[idx] = w2[(e * 24 + o) * 121 + k];
    }
}

// ---------------- S[b,o,k,Q] ----------------
__global__ void __launch_bounds__(256) s_kernel(const float* __restrict__ x,
                                                const float* __restrict__ w1) {
    extern __shared__ float sm[];
    float* xs = sm;               // 72 x 244 (dup-padded)
    float* ws = sm + 72 * 244;    // 24 x 72
    const int k = blockIdx.x, b = blockIdx.y;
    const int tid = threadIdx.x;

    for (int idx = tid; idx < 72 * 240; idx += 256) {
        int i = idx / 240, c = idx - 240 * i;
        xs[i * 244 + c] = x[(b * 72 + i) * 240 + c];
    }
    for (int idx = tid; idx < 72 * 4; idx += 256) {
        int i = idx >> 2, j = idx & 3;
        xs[i * 244 + 240 + j] = x[(b * 72 + i) * 240 + j];
    }
    for (int idx = tid; idx < 24 * 72; idx += 256)
        ws[idx] = w1[idx * 121 + k];
    __syncthreads();

    for (int task = tid; task < 360; task += 256) {
        int og = task / 60, qg = task - 60 * og;
        int o0 = og * 4, Q0 = qg * 4;
        float acc[4][4];
        #pragma unroll
        for (int a = 0; a < 4; a++)
            #pragma unroll
            for (int q = 0; q < 4; q++) acc[a][q] = 0.f;
        int base = Q0 + k + 120; if (base >= 240) base -= 240;
        const float* xb = xs + base;
        const float* wp0 = ws + (o0 + 0) * 72;
        const float* wp1 = ws + (o0 + 1) * 72;
        const float* wp2 = ws + (o0 + 2) * 72;
        const float* wp3 = ws + (o0 + 3) * 72;
        #pragma unroll 4
        for (int i = 0; i < 72; i++) {
            const float* xr = xb + i * 244;
            float x0 = xr[0], x1 = xr[1], x2 = xr[2], x3 = xr[3];
            float w0 = wp0[i], w1v = wp1[i], w2v = wp2[i], w3v = wp3[i];
            acc[0][0]=fmaf(w0,x0,acc[0][0]); acc[0][1]=fmaf(w0,x1,acc[0][1]);
            acc[0][2]=fmaf(w0,x2,acc[0][2]); acc[0][3]=fmaf(w0,x3,acc[0][3]);
            acc[1][0]=fmaf(w1v,x0,acc[1][0]); acc[1][1]=fmaf(w1v,x1,acc[1][1]);
            acc[1][2]=fmaf(w1v,x2,acc[1][2]); acc[1][3]=fmaf(w1v,x3,acc[1][3]);
            acc[2][0]=fmaf(w2v,x0,acc[2][0]); acc[2][1]=fmaf(w2v,x1,acc[2][1]);
            acc[2][2]=fmaf(w2v,x2,acc[2][2]); acc[2][3]=fmaf(w2v,x3,acc[2][3]);
            acc[3][0]=fmaf(w3v,x0,acc[3][0]); acc[3][1]=fmaf(w3v,x1,acc[3][1]);
            acc[3][2]=fmaf(w3v,x2,acc[3][2]); acc[3][3]=fmaf(w3v,x3,acc[3][3]);
        }
        size_t pbase = ((size_t)(b * 24 + o0) * 121 + k) * 240 + Q0;
        #pragma unroll
        for (int oo = 0; oo < 4; oo++)
            #pragma unroll
            for (int qq = 0; qq < 4; qq++)
                g_P[pbase + (size_t)oo * 121 * 240 + qq] = acc[oo][qq];
    }
}

// ---------------- prefix over k ----------------
__global__ void prefix_k() {
    int bo = blockIdx.x, Q = threadIdx.x;
    if (Q < 240) {
        size_t base = (size_t)bo * 121 * 240 + Q;
        float acc = 0.f;
        for (int k = 0; k < 121; k++) {
            acc += g_P[base + (size_t)k * 240];
            g_P[base + (size_t)k * 240] = acc;
        }
    }
}

// ---------------- encoder v2 ----------------
// block = 128 thr = 4 warps = 2 windows (2 warps each).
// conv1: warp handles 12 of 24 o's for its window.
// conv2/DFT/fc/ysin: warp handles 4 of 8 e's for its window (no cross-warp reduce).
// smem per window: hp 24x252 (zero-padded, f4-aligned rows) + lt 8x122 = 7024 floats.
__global__ void __launch_bounds__(128, 4) encode_k(
    const float* __restrict__ lna, const float* __restrict__ lnb,
    const float* __restrict__ b2, const float* __restrict__ fcw,
    const float* __restrict__ fcb, float* __restrict__ out)
{
    extern __shared__ float sm[];
    const int warp = threadIdx.x >> 5, lane = threadIdx.x & 31;
    const int wwin = warp >> 1, whalf = warp & 1;
    float* hpw = sm + wwin * 7024;
    float* lt  = hpw + 6048;
    const int s = blockIdx.x * 2 + wwin;
    const int b = s / 240, n = s - b * 240;

    // zero both windows' hp
    for (int i = threadIdx.x; i < 2 * 6048; i += 128) {
        int w2i = i / 6048, r = i - w2i * 6048;
        sm[w2i * 7024 + r] = 0.f;
    }
    __syncthreads();

    // ---- conv1 via prefix diffs + LayerNorm + tanh (12 o's per warp) ----
    const size_t pb0 = (size_t)(b * 24) * 121 * 240;
    for (int oo = 0; oo < 12; oo++) {
        int o = whalf * 12 + oo;
        const float* P = g_P + pb0 + (size_t)o * 121 * 240;
        float hv[4]; float s1 = 0.f, s2 = 0.f;
        #pragma unroll
        for (int j = 0; j < 4; j++) {
            int t = lane + 32 * j;
            float h = 0.f;
            if (t < 121) {
                int Q = n + t; if (Q >= 240) Q -= 240;
                if (t < 60) h = P[120 * 240 + Q] - P[(59 - t) * 240 + Q];
                else        h = P[(180 - t) * 240 + Q];
                s1 += h; s2 += h * h;
            }
            hv[j] = h;
        }
        s1 = wred(s1); s2 = wred(s2);
        float mean = s1 * (1.f / 121.f);
        float var = (s2 - s1 * mean) * (1.f / 120.f);
        float inv = 1.f / (sqrtf(var) + 1e-5f);
        #pragma unroll
        for (int j = 0; j < 4; j++) {
            int t = lane + 32 * j;
            if (t < 121)
                hpw[o * 252 + 60 + t] = tanhf((hv[j] - mean) * inv * lna[t] + lnb[t]);
        }
    }
    __syncthreads();

    // ---- conv2: 4 e's x 4 t's per lane, f32x2 packed over e-pairs ----
    const int ebase = whalf * 4;
    const int t0 = 4 * lane;
    unsigned long long acc2[2][4];
    #pragma unroll
    for (int p = 0; p < 2; p++)
        #pragma unroll
        for (int j = 0; j < 4; j++) acc2[p][j] = 0ull;

    for (int o = 0; o < 24; o++) {
        const float* hrow = hpw + o * 252 + t0;
        const ulonglong2* wp = (const ulonglong2*)(g_w2t + (size_t)o * 968 + ebase);
        float4 cur = *(const float4*)hrow;
        unsigned long long xd0 = dup2(cur.x), xd1 = dup2(cur.y),
                           xd2 = dup2(cur.z), xd3 = dup2(cur.w);
        #pragma unroll 2
        for (int g = 0; g < 30; g++) {
            float4 nxt = *(const float4*)(hrow + 4 * g + 4);
            {
                ulonglong2 w = wp[2 * (4 * g + 0)];
                ffma2(acc2[0][0], w.x, xd0); ffma2(acc2[0][1], w.x, xd1);
                ffma2(acc2[0][2], w.x, xd2); ffma2(acc2[0][3], w.x, xd3);
                ffma2(acc2[1][0], w.y, xd0); ffma2(acc2[1][1], w.y, xd1);
                ffma2(acc2[1][2], w.y, xd2); ffma2(acc2[1][3], w.y, xd3);
                xd0 = xd1; xd1 = xd2; xd2 = xd3; xd3 = dup2(nxt.x);
            }
            {
                ulonglong2 w = wp[2 * (4 * g + 1)];
                ffma2(acc2[0][0], w.x, xd0); ffma2(acc2[0][1], w.x, xd1);
                ffma2(acc2[0][2], w.x, xd2); ffma2(acc2[0][3], w.x, xd3);
                ffma2(acc2[1][0], w.y, xd0); ffma2(acc2[1][1], w.y, xd1);
                ffma2(acc2[1][2], w.y, xd2); ffma2(acc2[1][3], w.y, xd3);
                xd0 = xd1; xd1 = xd2; xd2 = xd3; xd3 = dup2(nxt.y);
            }
            {
                ulonglong2 w = wp[2 * (4 * g + 2)];
                ffma2(acc2[0][0], w.x, xd0); ffma2(acc2[0][1], w.x, xd1);
                ffma2(acc2[0][2], w.x, xd2); ffma2(acc2[0][3], w.x, xd3);
                ffma2(acc2[1][0], w.y, xd0); ffma2(acc2[1][1], w.y, xd1);
                ffma2(acc2[1][2], w.y, xd2); ffma2(acc2[1][3], w.y, xd3);
                xd0 = xd1; xd1 = xd2; xd2 = xd3; xd3 = dup2(nxt.z);
            }
            {
                ulonglong2 w = wp[2 * (4 * g + 3)];
                ffma2(acc2[0][0], w.x, xd0); ffma2(acc2[0][1], w.x, xd1);
                ffma2(acc2[0][2], w.x, xd2); ffma2(acc2[0][3], w.x, xd3);
                ffma2(acc2[1][0], w.y, xd0); ffma2(acc2[1][1], w.y, xd1);
                ffma2(acc2[1][2], w.y, xd2); ffma2(acc2[1][3], w.y, xd3);
                xd0 = xd1; xd1 = xd2; xd2 = xd3; xd3 = dup2(nxt.w);
            }
        }
        {   // k = 120
            ulonglong2 w = wp[2 * 120];
            ffma2(acc2[0][0], w.x, xd0); ffma2(acc2[0][1], w.x, xd1);
            ffma2(acc2[0][2], w.x, xd2); ffma2(acc2[0][3], w.x, xd3);
            ffma2(acc2[1][0], w.y, xd0); ffma2(acc2[1][1], w.y, xd1);
            ffma2(acc2[1][2], w.y, xd2); ffma2(acc2[1][3], w.y, xd3);
        }
    }
    #pragma unroll
    for (int p = 0; p < 2; p++) {
        int e0 = ebase + 2 * p;
        float be0 = b2[e0], be1 = b2[e0 + 1];
        #pragma unroll
        for (int j = 0; j < 4; j++) {
            int t = t0 + j;
            if (t < 121) {
                float2 v = unpack2(acc2[p][j]);
                lt[e0 * 122 + t]       = v.x + be0;
                lt[(e0 + 1) * 122 + t] = v.y + be1;
            }
        }
    }
    __syncwarp();

    // ---- DFT (bins 1..60 over lanes, 2 rounds), per-warp 4 e's ----
    float num[4] = {0.f, 0.f, 0.f, 0.f}, den[4] = {0.f, 0.f, 0.f, 0.f};
    #pragma unroll
    for (int round = 0; round < 2; round++) {
        int fi = lane + 32 * round;
        if (fi < 60) {
            float cr[4] = {0.f, 0.f, 0.f, 0.f}, ci[4] = {0.f, 0.f, 0.f, 0.f};
            for (int t = 0; t < 121; t++) {
                float2 w = g_twid[t * 64 + fi + 1];
                #pragma unroll
                for (int e = 0; e < 4; e++) {
                    float l = lt[(ebase + e) * 122 + t];
                    cr[e] = fmaf(l, w.x, cr[e]);
                    ci[e] = fmaf(l, w.y, ci[e]);
                }
            }
            float fr = 0.5f * (float)(fi + 1);
            #pragma unroll
            for (int e = 0; e < 4; e++) {
                float pw = cr[e] * cr[e] + ci[e] * ci[e];
                num[e] = fmaf(pw, fr, num[e]);
                den[e] += pw;
            }
        }
    }
    #pragma unroll
    for (int e = 0; e < 4; e++) { num[e] = wred(num[e]); den[e] = wred(den[e]); }

    // ---- fc phase + DC ----
    float bo_[4], v0[4], v1[4];
    #pragma unroll
    for (int e = 0; e < 4; e++) {
        int eg = ebase + e;
        float sb = 0.f, sv0 = 0.f, sv1 = 0.f;
        for (int t = lane; t < 121; t += 32) {
            float l = lt[eg * 122 + t];
            sb += l;
            sv0 = fmaf(l, fcw[(eg * 2 + 0) * 121 + t], sv0);
            sv1 = fmaf(l, fcw[(eg * 2 + 1) * 121 + t], sv1);
        }
        bo_[e] = wred(sb) * (1.f / 121.f);
        v0[e] = wred(sv0) + fcb[eg * 2];
        v1[e] = wred(sv1) + fcb[eg * 2 + 1];
    }

    float fe[4], am[4], ph[4];
    #pragma unroll
    for (int e = 0; e < 4; e++) {
        fe[e] = num[e] / den[e];
        am[e] = 2.f * sqrtf(den[e]) * (1.f / 121.f);
        ph[e] = atan2f(v1[e], v0[e]);
    }

    if (n == 0) {
        if (lane == 0) {
            #pragma unroll
            for (int e = 0; e < 4; e++) {
                int eg = ebase + e;
                out[OFF_P  + b * 8 + eg] = ph[e] * (1.f / TPIF);
                out[OFF_FQ + b * 8 + eg] = fe[e];
                out[OFF_A  + b * 8 + eg] = am[e];
                out[OFF_B  + b * 8 + eg] = bo_[e];
            }
        }
        #pragma unroll
        for (int e = 0; e < 4; e++) {
            int eg = ebase + e;
            for (int t = lane; t < 121; t += 32)
                out[OFF_LAT + (b * 8 + eg) * 121 + t] = lt[eg * 122 + t];
        }
    }

    // ---- sinusoid resynthesis ----
    #pragma unroll
    for (int e = 0; e < 4; e++) {
        int eg = ebase + e;
        float* yd = g_ys + ((size_t)(b * 8 + eg) * 240 + n) * 121;
        float w = TPIF * fe[e];
        for (int t = lane; t < 121; t += 32) {
            float arg = fmaf(w, (float)(t - 60) * (1.f / 60.f), ph[e]);
            yd[t] = fmaf(am[e], sinf(arg), bo_[e]);
        }
    }
}

// ---------------- overlap-add (deterministic gather) ----------------
__global__ void overlap_k(float* __restrict__ out) {
    int be = blockIdx.x;
    int j = threadIdx.x; // 0..359
    const float* ys = g_ys + (size_t)be * 240 * 121;
    int tlo = j - 239; if (tlo < 0) tlo = 0;
    int thi = j < 120 ? j : 120;
    float s = 0.f;
    for (int t = tlo; t <= thi; t++) s += ys[(j - t) * 121 + t];
    float w = (j < 121) ? (float)(j + 1) : (j > 239 ? (float)(360 - j) : 121.f);
    float sig = s / w;
    if (j < 121) out[OFF_SIG + be * 121 + j] = sig;
    g_scy[be * 360 + j] = (j >= 60 && j < 300) ? sig : 0.f;
}

// ---------------- decoder conv1 (bias skipped: cancels in BN) ----------------
__global__ void __launch_bounds__(256) dec1_k(const float* __restrict__ dw1) {
    __shared__ float ys[8 * 360], ws[8 * 121];
    int b = blockIdx.x, o = blockIdx.y, tid = threadIdx.x;
    for (int i = tid; i < 8 * 360; i += 256)
        ys[i] = g_scy[(b * 8 + i / 360) * 360 + i % 360];
    for (int i = tid; i < 8 * 121; i += 256)
        ws[i] = dw1[o * 8 * 121 + i];
    __syncthreads();
    if (tid < 240) {
        float acc = 0.f;
        #pragma unroll
        for (int e = 0; e < 8; e++) {
            const float* yr = ys + e * 360 + tid;
            const float* wr = ws + e * 121;
            #pragma unroll 4
            for (int k = 0; k < 121; k++) acc = fmaf(wr[k], yr[k], acc);
        }
        g_dpre[(b * 24 + o) * 240 + tid] = acc;
    }
}

// ---------------- BN stats (deterministic tree) ----------------
__global__ void bnstat_k() {
    __shared__ float r1[256], r2[256];
    int o = blockIdx.x, tid = threadIdx.x;
    float s1 = 0.f, s2 = 0.f;
    for (int i = tid; i < 3840; i += 256) {
        int bb = i / 240, t = i - 240 * bb;
        float v = g_dpre[(bb * 24 + o) * 240 + t];
        s1 += v; s2 += v * v;
    }
    r1[tid] = s1; r2[tid] = s2; __syncthreads();
    for (int st = 128; st > 0; st >>= 1) {
        if (tid < st) { r1[tid] += r1[tid + st]; r2[tid] += r2[tid + st]; }
        __syncthreads();
    }
    if (tid == 0) {
        float m = r1[0] * (1.f / 3840.f);
        g_bnm[o] = m;
        g_bni[o] = rsqrtf(r2[0] * (1.f / 3840.f) - m * m + 1e-5f);
    }
}

__global__ void bnapply_k(const float* __restrict__ gam, const float* __restrict__ bet) {
    int idx = blockIdx.x * blockDim.x + threadIdx.x;
    if (idx >= 16 * 24 * 360) return;
    int tau = idx % 360, bo = idx / 360;
    int o = bo % 24;
    float v = 0.f;
    if (tau >= 60 && tau < 300)
        v = tanhf((g_dpre[bo * 240 + tau - 60] - g_bnm[o]) * g_bni[o] * gam[o] + bet[o]);
    g_ddp[idx] = v;
}

// ---------------- decoder conv2 + outputs ----------------
__global__ void __launch_bounds__(64) dec2_k(const float* __restrict__ dw2,
                                             const float* __restrict__ db2,
                                             float* __restrict__ out) {
    __shared__ float dd[24 * 360], ws[24 * 121];
    int b = blockIdx.x, c = blockIdx.y, tid = threadIdx.x;
    for (int i = tid; i < 24 * 360; i += 64) dd[i] = g_ddp[b * 24 * 360 + i];
    for (int i = tid; i < 24 * 121; i += 64) ws[i] = dw2[c * 24 * 121 + i];
    __syncthreads();
    if (tid < 60) {
        int t0 = tid * 4;
        float a0 = 0.f, a1 = 0.f, a2 = 0.f, a3 = 0.f;
        for (int o = 0; o < 24; o++) {
            const float* dr = dd + o * 360 + t0;
            const float* wr = ws + o * 121;
            float x0 = dr[0], x1 = dr[1], x2 = dr[2];
            #pragma unroll 4
            for (int k = 0; k < 121; k++) {
                float w = wr[k]; float x3 = dr[k + 3];
                a0 = fmaf(w, x0, a0); a1 = fmaf(w, x1, a1);
                a2 = fmaf(w, x2, a2); a3 = fmaf(w, x3, a3);
                x0 = x1; x1 = x2; x2 = x3;
            }
        }
        float bias = db2[c];
        float r[4] = { a0 + bias, a1 + bias, a2 + bias, a3 + bias };
        size_t yb = (size_t)(b * 72 + c) * 240 + t0;
        #pragma unroll
        for (int q = 0; q < 4; q++) {
            out[OFF_Y + yb + q] = r[q];
            int t = t0 + q;
            if (t < 121) out[OFF_YP + (b * 72 + c) * 121 + t] = r[q];
        }
    }
}

// ---------------- launch ----------------
extern "C" void kernel_launch(void* const* d_in, const int* in_sizes, int n_in,
                              void* d_out, int out_size) {
    const float* x   = (const float*)d_in[0];
    const float* w1  = (const float*)d_in[1];
    const float* lna = (const float*)d_in[3];
    const float* lnb = (const float*)d_in[4];
    const float* w2  = (const float*)d_in[5];
    const float* b2  = (const float*)d_in[6];
    const float* fcw = (const float*)d_in[7];
    const float* fcb = (const float*)d_in[8];
    const float* dw1 = (const float*)d_in[9];
    const float* bng = (const float*)d_in[11];
    const float* bnb = (const float*)d_in[12];
    const float* dw2 = (const float*)d_in[13];
    const float* db2 = (const float*)d_in[14];
    float* out = (float*)d_out;

    const int SMEM_S = (72 * 244 + 24 * 72) * 4;      // 77184
    const int SMEM_E = 2 * 7024 * 4;                  // 56192
    cudaFuncSetAttribute(s_kernel, cudaFuncAttributeMaxDynamicSharedMemorySize, SMEM_S);
    cudaFuncSetAttribute(encode_k, cudaFuncAttributeMaxDynamicSharedMemorySize, SMEM_E);

    prep_k<<<64, 256>>>(w2);
    s_kernel<<<dim3(121, 16), 256, SMEM_S>>>(x, w1);
    prefix_k<<<384, 256>>>();
    encode_k<<<1920, 128, SMEM_E>>>(lna, lnb, b2, fcw, fcb, out);
    overlap_k<<<128, 360>>>(out);
    dec1_k<<<dim3(16, 24), 256>>>(dw1);
    bnstat_k<<<24, 256>>>();
    bnapply_k<<<540, 256>>>(bng, bnb);
    dec2_k<<<dim3(16, 72), 64>>>(dw2, db2, out);
}